// round 11
// baseline (speedup 1.0000x reference)
#include <cuda_runtime.h>
#include <cuda_fp16.h>
#include <cstdint>
#include <math_constants.h>

// Fixed dataset shape: N=50000, E=800000, Fin=128, H=C=64
#define NMAX 50048
#define EMAX 800000
#define HC   64

// ---------------- scratch (__device__ globals; no allocation allowed) --------------
__device__ __half2 g_h2[NMAX * 32];   // h = x @ W, fp16x2 (channel pairs)
__device__ float   g_x2[NMAX * HC];   // layer-2 input (fp32)
__device__ float   g_as[NMAX];        // alpha_src per node
__device__ float   g_ad[NMAX];        // alpha_dst per node
__device__ int     g_src[EMAX];       // edge src
__device__ int     g_dst[EMAX];       // edge dst
__device__ int     g_rank[EMAX];      // rank of edge within its dst row
__device__ int     g_deg[NMAX];       // in-degree histogram (zeroed by k_scan after use)
__device__ int     g_row[NMAX + 4];   // CSR row starts (int4-padded)
__device__ int     g_ssrc[EMAX];      // src ids grouped by dst

// packed f32x2 fma (sm_103a; ptxas never emits FFMA2 from C++)
__device__ __forceinline__ void fma2(unsigned long long& acc,
                                     unsigned long long x2, unsigned long long w2) {
    asm("fma.rn.f32x2 %0, %1, %2, %0;" : "+l"(acc) : "l"(x2), "l"(w2));
}
__device__ __forceinline__ unsigned long long dup2(float f) {
    unsigned long long r;
    asm("mov.b64 %0, {%1, %1};" : "=l"(r) : "f"(f));
    return r;
}
__device__ __forceinline__ uint32_t saddr(const void* p) {
    uint32_t a;
    asm("{ .reg .u64 t; cvta.to.shared.u64 t, %1; cvt.u32.u64 %0, t; }" : "=r"(a) : "l"(p));
    return a;
}
__device__ __forceinline__ void cp16(uint32_t dst, const void* src, bool pred) {
    int sz = pred ? 16 : 0;
    asm volatile("cp.async.cg.shared.global [%0], [%1], 16, %2;"
                 :: "r"(dst), "l"(src), "r"(sz));
}
#define CP_COMMIT() asm volatile("cp.async.commit_group;")
#define CP_WAIT(n)  asm volatile("cp.async.wait_group %0;" :: "n"(n))

// ---------------- GEMM body: BM=128, BN=64, 128 threads, 8x8 reg tile ---------------
template <int K>
__device__ void gemm_body(const float* __restrict__ X, const float* __restrict__ W,
                          const float* __restrict__ avs, const float* __restrict__ avd,
                          int N, int bid) {
    __shared__ float Xs[2][128 * 32];   // row-major [row][k]
    __shared__ float Ws[2][32 * 64];    // [k][col]
    int tid = threadIdx.x;
    int tx = tid & 7, ty = tid >> 3;
    int row0 = bid * 128;

    auto load_tile = [&](int buf, int k0) {
        int row = row0 + tid;
        bool ok = row < N;
        const float* src = X + (size_t)row * K + k0;
        uint32_t dst = saddr(&Xs[buf][tid * 32]);
#pragma unroll
        for (int j = 0; j < 8; j++) cp16(dst + j * 16, src + j * 4, ok);
#pragma unroll
        for (int j = 0; j < 4; j++) {
            int f = tid + j * 128;
            int k_l = f >> 4, col = (f & 15) * 4;
            cp16(saddr(&Ws[buf][k_l * 64 + col]), &W[(size_t)(k0 + k_l) * 64 + col], true);
        }
    };

    unsigned long long acc[8][4];
#pragma unroll
    for (int r = 0; r < 8; r++)
#pragma unroll
        for (int c = 0; c < 4; c++) acc[r][c] = 0ull;

    load_tile(0, 0);
    CP_COMMIT();

    const int NT = K / 32;
#pragma unroll
    for (int t = 0; t < NT; t++) {
        if (t + 1 < NT) {
            load_tile((t + 1) & 1, (t + 1) * 32);
            CP_COMMIT();
            CP_WAIT(1);
        } else {
            CP_WAIT(0);
        }
        __syncthreads();
        const float* xb = &Xs[t & 1][ty * 8 * 32];
        const float* wb = &Ws[t & 1][0];
#pragma unroll
        for (int kk = 0; kk < 32; kk += 4) {
            float4 xv[8];
#pragma unroll
            for (int r = 0; r < 8; r++)
                xv[r] = *reinterpret_cast<const float4*>(&xb[r * 32 + kk]);
#pragma unroll
            for (int j = 0; j < 4; j++) {
                ulonglong2 wa = *reinterpret_cast<const ulonglong2*>(&wb[(kk + j) * 64 + tx * 8]);
                ulonglong2 wc = *reinterpret_cast<const ulonglong2*>(&wb[(kk + j) * 64 + tx * 8 + 4]);
#pragma unroll
                for (int r = 0; r < 8; r++) {
                    unsigned long long x2 = dup2((&xv[r].x)[j]);
                    fma2(acc[r][0], x2, wa.x);
                    fma2(acc[r][1], x2, wa.y);
                    fma2(acc[r][2], x2, wc.x);
                    fma2(acc[r][3], x2, wc.y);
                }
            }
        }
        if (t + 1 < NT) __syncthreads();
    }

    float4 av0 = *reinterpret_cast<const float4*>(&avs[tx * 8]);
    float4 av1 = *reinterpret_cast<const float4*>(&avs[tx * 8 + 4]);
    float4 bv0 = *reinterpret_cast<const float4*>(&avd[tx * 8]);
    float4 bv1 = *reinterpret_cast<const float4*>(&avd[tx * 8 + 4]);
#pragma unroll
    for (int r = 0; r < 8; r++) {
        float a[8];
#pragma unroll
        for (int c = 0; c < 4; c++) {
            float lo, hi;
            asm("mov.b64 {%0, %1}, %2;" : "=f"(lo), "=f"(hi) : "l"(acc[r][c]));
            a[2 * c] = lo; a[2 * c + 1] = hi;
        }
        int row = row0 + ty * 8 + r;
        float s = a[0] * av0.x + a[1] * av0.y + a[2] * av0.z + a[3] * av0.w
                + a[4] * av1.x + a[5] * av1.y + a[6] * av1.z + a[7] * av1.w;
        float d = a[0] * bv0.x + a[1] * bv0.y + a[2] * bv0.z + a[3] * bv0.w
                + a[4] * bv1.x + a[5] * bv1.y + a[6] * bv1.z + a[7] * bv1.w;
#pragma unroll
        for (int o = 4; o > 0; o >>= 1) {
            s += __shfl_down_sync(0xFFFFFFFFu, s, o, 8);
            d += __shfl_down_sync(0xFFFFFFFFu, d, o, 8);
        }
        if (tx == 0 && row < N) { g_as[row] = s; g_ad[row] = d; }
        if (row < N) {
            __half2 h0 = __floats2half2_rn(a[0], a[1]);
            __half2 h1 = __floats2half2_rn(a[2], a[3]);
            __half2 h2 = __floats2half2_rn(a[4], a[5]);
            __half2 h3 = __floats2half2_rn(a[6], a[7]);
            uint4 pk;
            pk.x = *reinterpret_cast<uint32_t*>(&h0);
            pk.y = *reinterpret_cast<uint32_t*>(&h1);
            pk.z = *reinterpret_cast<uint32_t*>(&h2);
            pk.w = *reinterpret_cast<uint32_t*>(&h3);
            *reinterpret_cast<uint4*>(&g_h2[row * 32 + tx * 4]) = pk;
        }
    }
}

// ---------------- ingest body: dtype-detect + convert + histogram + rank -------------
__device__ void ingest_body(const void* __restrict__ eiv, int E, int N, int bid) {
    int i = bid * 128 + threadIdx.x;
    int e0 = i * 2;
    long long v0 = 0, v1 = 0;
    int ok = 1;
    if (e0 + 1 < E) {
        longlong2 v = ((const longlong2*)eiv)[i];
        v0 = v.x; v1 = v.y;
        ok = (v0 >= 0 && v0 < (long long)N && v1 >= 0 && v1 < (long long)N) ? 1 : 0;
    } else if (e0 < E) {
        v0 = ((const long long*)eiv)[e0];
        ok = (v0 >= 0 && v0 < (long long)N) ? 1 : 0;
    }
    int all64 = __syncthreads_and(ok);
    if (e0 >= E) return;
    int s0, s1 = 0, d0, d1 = 0;
    int has1 = (e0 + 1 < E);
    if (all64) {
        const long long* e = (const long long*)eiv;
        s0 = (int)v0;
        d0 = (int)e[E + e0];
        if (has1) { s1 = (int)v1; d1 = (int)e[E + e0 + 1]; }
    } else {
        const int* e = (const int*)eiv;
        s0 = e[e0];
        d0 = e[E + e0];
        if (has1) { s1 = e[e0 + 1]; d1 = e[E + e0 + 1]; }
    }
    s0 = min(max(s0, 0), N - 1); d0 = min(max(d0, 0), N - 1);
    g_src[e0] = s0; g_dst[e0] = d0;
    g_rank[e0] = atomicAdd(&g_deg[d0], 1);
    if (has1) {
        s1 = min(max(s1, 0), N - 1); d1 = min(max(d1, 0), N - 1);
        g_src[e0 + 1] = s1; g_dst[e0 + 1] = d1;
        g_rank[e0 + 1] = atomicAdd(&g_deg[d1], 1);
    }
}

// fat kernel: gemm1 blocks [0, ngemm) + ingest blocks [ngemm, ...)
__global__ __launch_bounds__(128)
void k_fat(const float* __restrict__ X, const float* __restrict__ W,
           const float* __restrict__ avs, const float* __restrict__ avd,
           const void* __restrict__ eiv, int N, int E, int ngemm) {
    if ((int)blockIdx.x < ngemm)
        gemm_body<128>(X, W, avs, avd, N, blockIdx.x);
    else
        ingest_body(eiv, E, N, blockIdx.x - ngemm);
}

__global__ __launch_bounds__(128)
void k_gemm2(const float* __restrict__ X, const float* __restrict__ W,
             const float* __restrict__ avs, const float* __restrict__ avd, int N) {
    gemm_body<64>(X, W, avs, avd, N, blockIdx.x);
}

// ---------------- scan (self-cleaning: zeroes g_deg after reading) -------------------
__global__ void k_scan() {
    __shared__ int warp_red[32];
    __shared__ int s_carry;
    int tid = threadIdx.x, lane = tid & 31, wid = tid >> 5;
    if (tid == 0) s_carry = 0;
    __syncthreads();
    int4* deg4 = (int4*)g_deg;
    int4* row4 = (int4*)g_row;
    const int total4 = NMAX / 4;
    for (int base = 0; base < total4; base += 1024) {
        int idx = base + tid;
        int4 v = (idx < total4) ? deg4[idx] : make_int4(0, 0, 0, 0);
        if (idx < total4) deg4[idx] = make_int4(0, 0, 0, 0);
        int s = v.x + v.y + v.z + v.w;
        int x = s;
#pragma unroll
        for (int o = 1; o < 32; o <<= 1) {
            int t = __shfl_up_sync(0xFFFFFFFFu, x, o);
            if (lane >= o) x += t;
        }
        if (lane == 31) warp_red[wid] = x;
        __syncthreads();
        if (wid == 0) {
            int w = warp_red[lane];
#pragma unroll
            for (int o = 1; o < 32; o <<= 1) {
                int t = __shfl_up_sync(0xFFFFFFFFu, w, o);
                if (lane >= o) w += t;
            }
            warp_red[lane] = w;
        }
        __syncthreads();
        int wsum = (wid > 0) ? warp_red[wid - 1] : 0;
        int incl = x + wsum;
        int carry = s_carry;
        if (idx < total4) {
            int e0 = carry + incl - s;
            int4 r;
            r.x = e0;
            r.y = e0 + v.x;
            r.z = e0 + v.x + v.y;
            r.w = e0 + v.x + v.y + v.z;
            row4[idx] = r;
        }
        __syncthreads();
        if (tid == 1023) s_carry = carry + incl;
        __syncthreads();
    }
}

// atomic-free scatter, 4 edges/thread (int4 loads; MLP=4)
__global__ void k_scatter(int E) {
    int i = blockIdx.x * 256 + threadIdx.x;
    int nvec = E >> 2;
    if (i < nvec) {
        int4 d = ((const int4*)g_dst)[i];
        int4 r = ((const int4*)g_rank)[i];
        int4 s = ((const int4*)g_src)[i];
        int b0 = g_row[d.x], b1 = g_row[d.y], b2 = g_row[d.z], b3 = g_row[d.w];
        g_ssrc[b0 + r.x] = s.x;
        g_ssrc[b1 + r.y] = s.y;
        g_ssrc[b2 + r.z] = s.z;
        g_ssrc[b3 + r.w] = s.w;
    } else if (i == nvec) {
        for (int e = nvec * 4; e < E; e++)
            g_ssrc[g_row[g_dst[e]] + g_rank[e]] = g_src[e];
    }
}

// ---------------- fused GAT aggregation: one warp per dst node, lean inner loop ------
// Shift-free softmax (scores O(1); fp32 exp cannot overflow).
// Out-of-range lanes carry p=0, so shfl'd weights self-gate: NO predicate/select in
// the inner loop. Accumulate with packed FFMA2; shfl row OFFSET (src*32), not id.
__global__ void k_gat(const float* __restrict__ bias, float* __restrict__ outbuf,
                      int do_relu, int N) {
    int warp = (blockIdx.x * blockDim.x + threadIdx.x) >> 5;
    int lane = threadIdx.x & 31;
    if (warp >= N) return;
    int beg = g_row[warp], end = g_row[warp + 1];
    float ad = g_ad[warp];
    const uint32_t* h2u = (const uint32_t*)g_h2;

    unsigned long long acc = 0ull;   // packed f32x2 accumulator (2 channels)
    float ssum = 0.f;
    for (int base = beg; base < end; base += 32) {
        int i = base + lane;
        float p = 0.f;
        int off = 0;
        if (i < end) {
            int srcl = g_ssrc[i];
            float e = g_as[srcl] + ad;
            e = (e > 0.f) ? e : 0.2f * e;      // LeakyReLU(0.2)
            p = __expf(e);
            ssum += p;
            off = srcl * 32;
        }
        int cnt = min(32, end - base);
        for (int c0 = 0; c0 < cnt; c0 += 8) {
            uint32_t hw[8];
            unsigned long long pw[8];
#pragma unroll
            for (int j = 0; j < 8; j++) {
                int jj = (c0 + j) & 31;
                float pv = __shfl_sync(0xFFFFFFFFu, p, jj);     // 0 beyond cnt
                int   ov = __shfl_sync(0xFFFFFFFFu, off, jj);
                pw[j] = dup2(pv);
                hw[j] = h2u[ov + lane];
            }
#pragma unroll
            for (int j = 0; j < 8; j++) {
                float2 hf = __half22float2(*reinterpret_cast<__half2*>(&hw[j]));
                unsigned long long h2p;
                asm("mov.b64 %0, {%1, %2};" : "=l"(h2p) : "f"(hf.x), "f"(hf.y));
                fma2(acc, h2p, pw[j]);
            }
        }
    }
#pragma unroll
    for (int o = 16; o > 0; o >>= 1)
        ssum += __shfl_xor_sync(0xFFFFFFFFu, ssum, o);

    float accx, accy;
    asm("mov.b64 {%0, %1}, %2;" : "=f"(accx), "=f"(accy) : "l"(acc));
    float inv = 1.f / (ssum + 1e-16f);   // deg==0: acc=0 -> out=bias, matches ref
    float2 bv = ((const float2*)bias)[lane];
    float2 r;
    r.x = accx * inv + bv.x;
    r.y = accy * inv + bv.y;
    if (do_relu) { r.x = fmaxf(r.x, 0.f); r.y = fmaxf(r.y, 0.f); }
    ((float2*)outbuf)[warp * 32 + lane] = r;
}

// ---------------- launch -------------------------------------------------------------
extern "C" void kernel_launch(void* const* d_in, const int* in_sizes, int n_in,
                              void* d_out, int out_size) {
    // ---- size-driven role assignment (robust to metadata ordering) ----
    int ix = 0, ie = 0, iw1 = 0, iw2 = 0;
    for (int i = 1; i < n_in; i++) if (in_sizes[i] > in_sizes[ix]) ix = i;
    ie = (ix == 0) ? 1 : 0;
    for (int i = 0; i < n_in; i++) if (i != ix && in_sizes[i] > in_sizes[ie]) ie = i;
    iw1 = -1;
    for (int i = 0; i < n_in; i++) {
        if (i == ix || i == ie) continue;
        if (iw1 < 0 || in_sizes[i] > in_sizes[iw1]) iw1 = i;
    }
    iw2 = -1;
    for (int i = 0; i < n_in; i++) {
        if (i == ix || i == ie || i == iw1) continue;
        if (iw2 < 0 || in_sizes[i] > in_sizes[iw2]) iw2 = i;
    }
    int rv[6]; int nrv = 0;
    for (int i = 0; i < n_in && nrv < 6; i++)
        if (i != ix && i != ie && i != iw1 && i != iw2) rv[nrv++] = i;

    int ias1, iad1, ib1, ias2, iad2, ib2;
    if (ix == 0) {  // signature/dict order
        ias1 = rv[0]; iad1 = rv[1]; ib1 = rv[2];
        ias2 = rv[3]; iad2 = rv[4]; ib2 = rv[5];
    } else {        // alphabetical order
        iad1 = rv[0]; iad2 = rv[1]; ias1 = rv[2];
        ias2 = rv[3]; ib1  = rv[4]; ib2  = rv[5];
    }

    const float* x   = (const float*)d_in[ix];
    const void*  ei  = d_in[ie];
    const float* W1  = (const float*)d_in[iw1];
    const float* as1 = (const float*)d_in[ias1];
    const float* ad1 = (const float*)d_in[iad1];
    const float* b1  = (const float*)d_in[ib1];
    const float* W2  = (const float*)d_in[iw2];
    const float* as2 = (const float*)d_in[ias2];
    const float* ad2 = (const float*)d_in[iad2];
    const float* b2  = (const float*)d_in[ib2];
    float*       out = (float*)d_out;

    const int Hd  = in_sizes[ias1];         // 64
    const int Fin = in_sizes[iw1] / Hd;     // 128
    const int N   = in_sizes[ix] / Fin;     // 50000
    const int E   = in_sizes[ie] / 2;       // 800000

    float* p_x2 = nullptr;
    cudaGetSymbolAddress((void**)&p_x2, g_x2);

    const int NGEMM   = (N + 127) / 128;
    const int NINGEST = (E + 255) / 256;
    const int B_E4    = (E / 4 + 1 + 255) / 256;
    const int B_WARP  = (N * 32 + 255) / 256;

    // 6 launches; slot 4 (= ncu capture window) lands on k_gat (layer 1).
    k_fat<<<NGEMM + NINGEST, 128>>>(x, W1, as1, ad1, ei, N, E, NGEMM);  // 1
    k_scan<<<1, 1024>>>();                                              // 2
    k_scatter<<<B_E4, 256>>>(E);                                        // 3
    k_gat<<<B_WARP, 256>>>(b1, p_x2, 1, N);                             // 4 <- profiled
    k_gemm2<<<NGEMM, 128>>>(p_x2, W2, as2, ad2, N);                     // 5
    k_gat<<<B_WARP, 256>>>(b2, out, 0, N);                              // 6
}

// round 12
// speedup vs baseline: 1.0340x; 1.0340x over previous
#include <cuda_runtime.h>
#include <cuda_fp16.h>
#include <cstdint>
#include <math_constants.h>

// Fixed dataset shape: N=50000, E=800000, Fin=128, H=C=64
#define NMAX 50048
#define EMAX 800000
#define HC   64

typedef unsigned long long ull;

// ---------------- scratch (__device__ globals; no allocation allowed) --------------
__device__ __half2 g_h2[NMAX * 32];   // h = x @ W, fp16x2 (channel pairs)
__device__ float   g_x2[NMAX * HC];   // layer-2 input (fp32)
__device__ float   g_as[NMAX];        // alpha_src per node
__device__ float   g_ad[NMAX];        // alpha_dst per node
__device__ int     g_src[EMAX];       // edge src
__device__ int     g_dst[EMAX];       // edge dst
__device__ int     g_rank[EMAX];      // rank of edge within its dst row
__device__ int     g_deg[NMAX];       // in-degree histogram (zeroed by k_scan after use)
__device__ int     g_row[NMAX + 4];   // CSR row starts (int4-padded)
__device__ int     g_ssrc[EMAX];      // src ids grouped by dst

// packed f32x2 fma (sm_103a; ptxas never emits FFMA2 from C++)
__device__ __forceinline__ void fma2(ull& acc, ull x2, ull w2) {
    asm("fma.rn.f32x2 %0, %1, %2, %0;" : "+l"(acc) : "l"(x2), "l"(w2));
}
__device__ __forceinline__ ull dup2(float f) {
    ull r;
    asm("mov.b64 %0, {%1, %1};" : "=l"(r) : "f"(f));
    return r;
}

// ---------------- ingest: dtype-detect + convert + histogram + rank -----------------
// 2 edges/thread. Dtype vote: read edge pair AS longlong2 (spans exactly the int32
// buffer bytes — safe both ways). int64 data: every value in [0,N) -> block votes
// int64; int32 data: adjacent pairs combine to lo + hi*2^32 -> essentially never.
__global__ void k_ingest(const void* __restrict__ eiv, int E, int N) {
    int i = blockIdx.x * 256 + threadIdx.x;
    int e0 = i * 2;
    long long v0 = 0, v1 = 0;
    int ok = 1;
    if (e0 + 1 < E) {
        longlong2 v = ((const longlong2*)eiv)[i];
        v0 = v.x; v1 = v.y;
        ok = (v0 >= 0 && v0 < (long long)N && v1 >= 0 && v1 < (long long)N) ? 1 : 0;
    } else if (e0 < E) {
        v0 = ((const long long*)eiv)[e0];
        ok = (v0 >= 0 && v0 < (long long)N) ? 1 : 0;
    }
    int all64 = __syncthreads_and(ok);
    if (e0 >= E) return;
    int s0, s1 = 0, d0, d1 = 0;
    int has1 = (e0 + 1 < E);
    if (all64) {
        const long long* e = (const long long*)eiv;
        s0 = (int)v0;
        d0 = (int)e[E + e0];
        if (has1) { s1 = (int)v1; d1 = (int)e[E + e0 + 1]; }
    } else {
        const int* e = (const int*)eiv;
        s0 = e[e0];
        d0 = e[E + e0];
        if (has1) { s1 = e[e0 + 1]; d1 = e[E + e0 + 1]; }
    }
    s0 = min(max(s0, 0), N - 1); d0 = min(max(d0, 0), N - 1);
    g_src[e0] = s0; g_dst[e0] = d0;
    g_rank[e0] = atomicAdd(&g_deg[d0], 1);
    if (has1) {
        s1 = min(max(s1, 0), N - 1); d1 = min(max(d1, 0), N - 1);
        g_src[e0 + 1] = s1; g_dst[e0 + 1] = d1;
        g_rank[e0 + 1] = atomicAdd(&g_deg[d1], 1);
    }
}

// ---------------- scan (self-cleaning: zeroes g_deg after reading) -------------------
__global__ void k_scan() {
    __shared__ int warp_red[32];
    __shared__ int s_carry;
    int tid = threadIdx.x, lane = tid & 31, wid = tid >> 5;
    if (tid == 0) s_carry = 0;
    __syncthreads();
    int4* deg4 = (int4*)g_deg;
    int4* row4 = (int4*)g_row;
    const int total4 = NMAX / 4;
    for (int base = 0; base < total4; base += 1024) {
        int idx = base + tid;
        int4 v = (idx < total4) ? deg4[idx] : make_int4(0, 0, 0, 0);
        if (idx < total4) deg4[idx] = make_int4(0, 0, 0, 0);
        int s = v.x + v.y + v.z + v.w;
        int x = s;
#pragma unroll
        for (int o = 1; o < 32; o <<= 1) {
            int t = __shfl_up_sync(0xFFFFFFFFu, x, o);
            if (lane >= o) x += t;
        }
        if (lane == 31) warp_red[wid] = x;
        __syncthreads();
        if (wid == 0) {
            int w = warp_red[lane];
#pragma unroll
            for (int o = 1; o < 32; o <<= 1) {
                int t = __shfl_up_sync(0xFFFFFFFFu, w, o);
                if (lane >= o) w += t;
            }
            warp_red[lane] = w;
        }
        __syncthreads();
        int wsum = (wid > 0) ? warp_red[wid - 1] : 0;
        int incl = x + wsum;
        int carry = s_carry;
        if (idx < total4) {
            int e0 = carry + incl - s;
            int4 r;
            r.x = e0;
            r.y = e0 + v.x;
            r.z = e0 + v.x + v.y;
            r.w = e0 + v.x + v.y + v.z;
            row4[idx] = r;
        }
        __syncthreads();
        if (tid == 1023) s_carry = carry + incl;
        __syncthreads();
    }
}

// atomic-free scatter, 4 edges/thread (int4 loads; MLP=4)
__global__ void k_scatter(int E) {
    int i = blockIdx.x * 256 + threadIdx.x;
    int nvec = E >> 2;
    if (i < nvec) {
        int4 d = ((const int4*)g_dst)[i];
        int4 r = ((const int4*)g_rank)[i];
        int4 s = ((const int4*)g_src)[i];
        int b0 = g_row[d.x], b1 = g_row[d.y], b2 = g_row[d.z], b3 = g_row[d.w];
        g_ssrc[b0 + r.x] = s.x;
        g_ssrc[b1 + r.y] = s.y;
        g_ssrc[b2 + r.z] = s.z;
        g_ssrc[b3 + r.w] = s.w;
    } else if (i == nvec) {
        for (int e = nvec * 4; e < E; e++)
            g_ssrc[g_row[g_dst[e]] + g_rank[e]] = g_src[e];
    }
}

// ---------------- GEMM: transposed-Xs compute + register-staged prefetch ------------
// H[N,64] = X[N,K] @ W[K,64]. BM=128, BN=64, 256 threads, 8x4 register tile.
// Tile t's global loads (LDG -> regs) are issued right after the sync that opens
// tile t-1's compute phase, so DRAM/L2 latency overlaps ~700 issue-cycles of FFMA2.
template <int K>
__launch_bounds__(256)
__global__ void k_gemm(const float* __restrict__ X, const float* __restrict__ W,
                       const float* __restrict__ avs, const float* __restrict__ avd,
                       int N) {
    const int XS = 132;                  // stride: 128 + 4 pad
    __shared__ float Xs[32 * XS];        // [k][row] transposed
    __shared__ float Ws[32 * 64];        // [k][col]
    int tid = threadIdx.x;
    int tx = tid & 15, ty = tid >> 4;
    int row0 = blockIdx.x * 128;

    int xrow = tid >> 3;                 // 0..31
    int xk   = (tid & 7) * 4;            // 0,4,..,28
    float4 xst[4];
    float4 wst[2];

    auto stage = [&](int k0) {
#pragma unroll
        for (int p = 0; p < 4; p++) {
            int row = row0 + xrow + p * 32;
            xst[p] = (row < N)
                ? *reinterpret_cast<const float4*>(&X[(size_t)row * K + k0 + xk])
                : make_float4(0.f, 0.f, 0.f, 0.f);
        }
#pragma unroll
        for (int j = 0; j < 2; j++) {
            int f = tid + j * 256;
            int k_l = f >> 4, c4 = (f & 15) * 4;
            wst[j] = *reinterpret_cast<const float4*>(&W[(size_t)(k0 + k_l) * 64 + c4]);
        }
    };
    auto commit = [&]() {
#pragma unroll
        for (int p = 0; p < 4; p++) {
            int row_l = xrow + p * 32;
            Xs[(xk + 0) * XS + row_l] = xst[p].x;
            Xs[(xk + 1) * XS + row_l] = xst[p].y;
            Xs[(xk + 2) * XS + row_l] = xst[p].z;
            Xs[(xk + 3) * XS + row_l] = xst[p].w;
        }
#pragma unroll
        for (int j = 0; j < 2; j++) {
            int f = tid + j * 256;
            int k_l = f >> 4, c4 = (f & 15) * 4;
            *reinterpret_cast<float4*>(&Ws[k_l * 64 + c4]) = wst[j];
        }
    };

    ull acc[4][4];                       // [row-pair][col], packed f32x2 over rows
#pragma unroll
    for (int rp = 0; rp < 4; rp++)
#pragma unroll
        for (int c = 0; c < 4; c++) acc[rp][c] = 0ull;

    stage(0);
    const int NT = K / 32;
#pragma unroll
    for (int t = 0; t < NT; t++) {
        commit();
        __syncthreads();
        if (t + 1 < NT) stage((t + 1) * 32);   // LDGs overlap compute below
#pragma unroll
        for (int k = 0; k < 32; k++) {
            ulonglong2 xa = *reinterpret_cast<const ulonglong2*>(&Xs[k * XS + ty * 8]);
            ulonglong2 xb = *reinterpret_cast<const ulonglong2*>(&Xs[k * XS + ty * 8 + 4]);
            float4 wv = *reinterpret_cast<const float4*>(&Ws[k * 64 + tx * 4]);
            ull w2[4];
            w2[0] = dup2(wv.x); w2[1] = dup2(wv.y);
            w2[2] = dup2(wv.z); w2[3] = dup2(wv.w);
#pragma unroll
            for (int c = 0; c < 4; c++) {
                fma2(acc[0][c], xa.x, w2[c]);
                fma2(acc[1][c], xa.y, w2[c]);
                fma2(acc[2][c], xb.x, w2[c]);
                fma2(acc[3][c], xb.y, w2[c]);
            }
        }
        __syncthreads();
    }

    // epilogue: a[i][j] = H[row0 + ty*8 + i][tx*4 + j]
    float a[8][4];
#pragma unroll
    for (int rp = 0; rp < 4; rp++)
#pragma unroll
        for (int c = 0; c < 4; c++) {
            float lo, hi;
            asm("mov.b64 {%0, %1}, %2;" : "=f"(lo), "=f"(hi) : "l"(acc[rp][c]));
            a[rp * 2 + 0][c] = lo;
            a[rp * 2 + 1][c] = hi;
        }

    float avs4[4], avd4[4];
#pragma unroll
    for (int j = 0; j < 4; j++) {
        avs4[j] = __ldg(&avs[tx * 4 + j]);
        avd4[j] = __ldg(&avd[tx * 4 + j]);
    }
#pragma unroll
    for (int i = 0; i < 8; i++) {
        int row = row0 + ty * 8 + i;
        float s = a[i][0] * avs4[0] + a[i][1] * avs4[1] + a[i][2] * avs4[2] + a[i][3] * avs4[3];
        float d = a[i][0] * avd4[0] + a[i][1] * avd4[1] + a[i][2] * avd4[2] + a[i][3] * avd4[3];
#pragma unroll
        for (int o = 8; o > 0; o >>= 1) {
            s += __shfl_down_sync(0xFFFFFFFFu, s, o, 16);
            d += __shfl_down_sync(0xFFFFFFFFu, d, o, 16);
        }
        if (tx == 0 && row < N) { g_as[row] = s; g_ad[row] = d; }
        if (row < N) {
            __half2 h01 = __floats2half2_rn(a[i][0], a[i][1]);
            __half2 h23 = __floats2half2_rn(a[i][2], a[i][3]);
            uint2 pk = make_uint2(*reinterpret_cast<uint32_t*>(&h01),
                                  *reinterpret_cast<uint32_t*>(&h23));
            *reinterpret_cast<uint2*>(&g_h2[row * 32 + tx * 2]) = pk;
        }
    }
}

// ---------------- fused GAT aggregation: one warp per dst node (R10 proven form) ----
// Shift-free softmax (scores O(1); fp32 exp cannot overflow). MLP-8 gather batching.
__global__ void k_gat(const float* __restrict__ bias, float* __restrict__ outbuf,
                      int do_relu, int N) {
    int warp = (blockIdx.x * blockDim.x + threadIdx.x) >> 5;
    int lane = threadIdx.x & 31;
    if (warp >= N) return;
    int beg = g_row[warp], end = g_row[warp + 1];
    float ad = g_ad[warp];
    const uint32_t* h2u = (const uint32_t*)g_h2;

    float accx = 0.f, accy = 0.f, ssum = 0.f;
    for (int base = beg; base < end; base += 32) {
        int i = base + lane;
        int srcl = 0;
        float p = 0.f;
        if (i < end) {
            srcl = g_ssrc[i];
            float e = g_as[srcl] + ad;
            e = (e > 0.f) ? e : 0.2f * e;      // LeakyReLU(0.2)
            p = __expf(e);
            ssum += p;
        }
        int cnt = min(32, end - base);
        for (int c0 = 0; c0 < cnt; c0 += 8) {
            uint32_t hw[8]; float pw[8];
#pragma unroll
            for (int j = 0; j < 8; j++) {
                int jj = c0 + j;
                float pv = __shfl_sync(0xFFFFFFFFu, p, jj & 31);
                int   sv = __shfl_sync(0xFFFFFFFFu, srcl, jj & 31);
                pw[j] = (jj < cnt) ? pv : 0.f;
                hw[j] = h2u[sv * 32 + lane];
            }
#pragma unroll
            for (int j = 0; j < 8; j++) {
                float2 hv = __half22float2(*reinterpret_cast<__half2*>(&hw[j]));
                accx += pw[j] * hv.x;
                accy += pw[j] * hv.y;
            }
        }
    }
#pragma unroll
    for (int o = 16; o > 0; o >>= 1)
        ssum += __shfl_xor_sync(0xFFFFFFFFu, ssum, o);

    float inv = 1.f / (ssum + 1e-16f);   // deg==0: acc=0 -> out=bias, matches ref
    float2 bv = ((const float2*)bias)[lane];
    float2 r;
    r.x = accx * inv + bv.x;
    r.y = accy * inv + bv.y;
    if (do_relu) { r.x = fmaxf(r.x, 0.f); r.y = fmaxf(r.y, 0.f); }
    ((float2*)outbuf)[warp * 32 + lane] = r;
}

// ---------------- launch -------------------------------------------------------------
extern "C" void kernel_launch(void* const* d_in, const int* in_sizes, int n_in,
                              void* d_out, int out_size) {
    // ---- size-driven role assignment (robust to metadata ordering) ----
    int ix = 0, ie = 0, iw1 = 0, iw2 = 0;
    for (int i = 1; i < n_in; i++) if (in_sizes[i] > in_sizes[ix]) ix = i;
    ie = (ix == 0) ? 1 : 0;
    for (int i = 0; i < n_in; i++) if (i != ix && in_sizes[i] > in_sizes[ie]) ie = i;
    iw1 = -1;
    for (int i = 0; i < n_in; i++) {
        if (i == ix || i == ie) continue;
        if (iw1 < 0 || in_sizes[i] > in_sizes[iw1]) iw1 = i;
    }
    iw2 = -1;
    for (int i = 0; i < n_in; i++) {
        if (i == ix || i == ie || i == iw1) continue;
        if (iw2 < 0 || in_sizes[i] > in_sizes[iw2]) iw2 = i;
    }
    int rv[6]; int nrv = 0;
    for (int i = 0; i < n_in && nrv < 6; i++)
        if (i != ix && i != ie && i != iw1 && i != iw2) rv[nrv++] = i;

    int ias1, iad1, ib1, ias2, iad2, ib2;
    if (ix == 0) {  // signature/dict order
        ias1 = rv[0]; iad1 = rv[1]; ib1 = rv[2];
        ias2 = rv[3]; iad2 = rv[4]; ib2 = rv[5];
    } else {        // alphabetical order
        iad1 = rv[0]; iad2 = rv[1]; ias1 = rv[2];
        ias2 = rv[3]; ib1  = rv[4]; ib2  = rv[5];
    }

    const float* x   = (const float*)d_in[ix];
    const void*  ei  = d_in[ie];
    const float* W1  = (const float*)d_in[iw1];
    const float* as1 = (const float*)d_in[ias1];
    const float* ad1 = (const float*)d_in[iad1];
    const float* b1  = (const float*)d_in[ib1];
    const float* W2  = (const float*)d_in[iw2];
    const float* as2 = (const float*)d_in[ias2];
    const float* ad2 = (const float*)d_in[iad2];
    const float* b2  = (const float*)d_in[ib2];
    float*       out = (float*)d_out;

    const int Hd  = in_sizes[ias1];         // 64
    const int Fin = in_sizes[iw1] / Hd;     // 128
    const int N   = in_sizes[ix] / Fin;     // 50000
    const int E   = in_sizes[ie] / 2;       // 800000

    float* p_x2 = nullptr;
    cudaGetSymbolAddress((void**)&p_x2, g_x2);

    const int B_E2   = (E / 2 + 255) / 256;
    const int B_E4   = (E / 4 + 1 + 255) / 256;
    const int B_WARP = (N * 32 + 255) / 256;
    const int B_GEMM = (N + 127) / 128;

    // 7 launches; slot 4 (= ncu capture window) lands on the NEW k_gemm<128>.
    k_ingest<<<B_E2, 256>>>(ei, E, N);                     // 1
    k_scan<<<1, 1024>>>();                                 // 2
    k_scatter<<<B_E4, 256>>>(E);                           // 3
    k_gemm<128><<<B_GEMM, 256>>>(x, W1, as1, ad1, N);      // 4 <- profiled
    k_gat<<<B_WARP, 256>>>(b1, p_x2, 1, N);                // 5
    k_gemm<64><<<B_GEMM, 256>>>(p_x2, W2, as2, ad2, N);    // 6
    k_gat<<<B_WARP, 256>>>(b2, out, 0, N);                 // 7
}

// round 13
// speedup vs baseline: 1.1725x; 1.1340x over previous
#include <cuda_runtime.h>
#include <cuda_fp16.h>
#include <cstdint>
#include <math_constants.h>

// Fixed dataset shape: N=50000, E=800000, Fin=128, H=C=64
#define NMAX 50048
#define EMAX 800000
#define HC   64

typedef unsigned long long ull;

// ---------------- scratch (__device__ globals; no allocation allowed) --------------
__device__ __half2 g_h2[NMAX * 32];   // h = x @ W, fp16x2 (channel pairs)
__device__ float   g_x2[NMAX * HC];   // layer-2 input (fp32)
__device__ float   g_as[NMAX];        // alpha_src per node
__device__ float   g_ad[NMAX];        // alpha_dst per node
__device__ int     g_src[EMAX];       // edge src
__device__ int     g_dst[EMAX];       // edge dst
__device__ int     g_rank[EMAX];      // rank of edge within its dst row
__device__ int     g_deg[NMAX];       // in-degree histogram (zeroed by k_scan after use)
__device__ int     g_row[NMAX + 4];   // CSR row starts (int4-padded)
__device__ int     g_ssrc[EMAX];      // src ids grouped by dst

// packed f32x2 fma (sm_103a; ptxas never emits FFMA2 from C++)
__device__ __forceinline__ void fma2(ull& acc, ull x2, ull w2) {
    asm("fma.rn.f32x2 %0, %1, %2, %0;" : "+l"(acc) : "l"(x2), "l"(w2));
}
__device__ __forceinline__ ull dup2(float f) {
    ull r;
    asm("mov.b64 %0, {%1, %1};" : "=l"(r) : "f"(f));
    return r;
}

// ---------------- GEMM body (R12 proven): prefetch + transposed Xs + FFMA2 ----------
template <int K>
__device__ void gemm_body(const float* __restrict__ X, const float* __restrict__ W,
                          const float* __restrict__ avs, const float* __restrict__ avd,
                          int N, int bid) {
    const int XS = 132;                  // stride: 128 + 4 pad
    __shared__ float Xs[32 * XS];        // [k][row] transposed
    __shared__ float Ws[32 * 64];        // [k][col]
    int tid = threadIdx.x;
    int tx = tid & 15, ty = tid >> 4;
    int row0 = bid * 128;

    int xrow = tid >> 3;
    int xk   = (tid & 7) * 4;
    float4 xst[4];
    float4 wst[2];

    auto stage = [&](int k0) {
#pragma unroll
        for (int p = 0; p < 4; p++) {
            int row = row0 + xrow + p * 32;
            xst[p] = (row < N)
                ? *reinterpret_cast<const float4*>(&X[(size_t)row * K + k0 + xk])
                : make_float4(0.f, 0.f, 0.f, 0.f);
        }
#pragma unroll
        for (int j = 0; j < 2; j++) {
            int f = tid + j * 256;
            int k_l = f >> 4, c4 = (f & 15) * 4;
            wst[j] = *reinterpret_cast<const float4*>(&W[(size_t)(k0 + k_l) * 64 + c4]);
        }
    };
    auto commit = [&]() {
#pragma unroll
        for (int p = 0; p < 4; p++) {
            int row_l = xrow + p * 32;
            Xs[(xk + 0) * XS + row_l] = xst[p].x;
            Xs[(xk + 1) * XS + row_l] = xst[p].y;
            Xs[(xk + 2) * XS + row_l] = xst[p].z;
            Xs[(xk + 3) * XS + row_l] = xst[p].w;
        }
#pragma unroll
        for (int j = 0; j < 2; j++) {
            int f = tid + j * 256;
            int k_l = f >> 4, c4 = (f & 15) * 4;
            *reinterpret_cast<float4*>(&Ws[k_l * 64 + c4]) = wst[j];
        }
    };

    ull acc[4][4];
#pragma unroll
    for (int rp = 0; rp < 4; rp++)
#pragma unroll
        for (int c = 0; c < 4; c++) acc[rp][c] = 0ull;

    stage(0);
    const int NT = K / 32;
#pragma unroll
    for (int t = 0; t < NT; t++) {
        commit();
        __syncthreads();
        if (t + 1 < NT) stage((t + 1) * 32);   // LDGs overlap compute below
#pragma unroll
        for (int k = 0; k < 32; k++) {
            ulonglong2 xa = *reinterpret_cast<const ulonglong2*>(&Xs[k * XS + ty * 8]);
            ulonglong2 xb = *reinterpret_cast<const ulonglong2*>(&Xs[k * XS + ty * 8 + 4]);
            float4 wv = *reinterpret_cast<const float4*>(&Ws[k * 64 + tx * 4]);
            ull w2[4];
            w2[0] = dup2(wv.x); w2[1] = dup2(wv.y);
            w2[2] = dup2(wv.z); w2[3] = dup2(wv.w);
#pragma unroll
            for (int c = 0; c < 4; c++) {
                fma2(acc[0][c], xa.x, w2[c]);
                fma2(acc[1][c], xa.y, w2[c]);
                fma2(acc[2][c], xb.x, w2[c]);
                fma2(acc[3][c], xb.y, w2[c]);
            }
        }
        __syncthreads();
    }

    float a[8][4];
#pragma unroll
    for (int rp = 0; rp < 4; rp++)
#pragma unroll
        for (int c = 0; c < 4; c++) {
            float lo, hi;
            asm("mov.b64 {%0, %1}, %2;" : "=f"(lo), "=f"(hi) : "l"(acc[rp][c]));
            a[rp * 2 + 0][c] = lo;
            a[rp * 2 + 1][c] = hi;
        }

    float avs4[4], avd4[4];
#pragma unroll
    for (int j = 0; j < 4; j++) {
        avs4[j] = __ldg(&avs[tx * 4 + j]);
        avd4[j] = __ldg(&avd[tx * 4 + j]);
    }
#pragma unroll
    for (int i = 0; i < 8; i++) {
        int row = row0 + ty * 8 + i;
        float s = a[i][0] * avs4[0] + a[i][1] * avs4[1] + a[i][2] * avs4[2] + a[i][3] * avs4[3];
        float d = a[i][0] * avd4[0] + a[i][1] * avd4[1] + a[i][2] * avd4[2] + a[i][3] * avd4[3];
#pragma unroll
        for (int o = 8; o > 0; o >>= 1) {
            s += __shfl_down_sync(0xFFFFFFFFu, s, o, 16);
            d += __shfl_down_sync(0xFFFFFFFFu, d, o, 16);
        }
        if (tx == 0 && row < N) { g_as[row] = s; g_ad[row] = d; }
        if (row < N) {
            __half2 h01 = __floats2half2_rn(a[i][0], a[i][1]);
            __half2 h23 = __floats2half2_rn(a[i][2], a[i][3]);
            uint2 pk = make_uint2(*reinterpret_cast<uint32_t*>(&h01),
                                  *reinterpret_cast<uint32_t*>(&h23));
            *reinterpret_cast<uint2*>(&g_h2[row * 32 + tx * 2]) = pk;
        }
    }
}

// ---------------- ingest body: dtype-detect + convert + histogram + rank -------------
// 2 edges/thread, 256 threads -> 512 edges/block. Dtype vote: read edge pair AS
// longlong2 (spans exactly the int32 buffer bytes — safe both ways).
__device__ void ingest_body(const void* __restrict__ eiv, int E, int N, int bid) {
    int i = bid * 256 + threadIdx.x;
    int e0 = i * 2;
    long long v0 = 0, v1 = 0;
    int ok = 1;
    if (e0 + 1 < E) {
        longlong2 v = ((const longlong2*)eiv)[i];
        v0 = v.x; v1 = v.y;
        ok = (v0 >= 0 && v0 < (long long)N && v1 >= 0 && v1 < (long long)N) ? 1 : 0;
    } else if (e0 < E) {
        v0 = ((const long long*)eiv)[e0];
        ok = (v0 >= 0 && v0 < (long long)N) ? 1 : 0;
    }
    int all64 = __syncthreads_and(ok);
    if (e0 >= E) return;
    int s0, s1 = 0, d0, d1 = 0;
    int has1 = (e0 + 1 < E);
    if (all64) {
        const long long* e = (const long long*)eiv;
        s0 = (int)v0;
        d0 = (int)e[E + e0];
        if (has1) { s1 = (int)v1; d1 = (int)e[E + e0 + 1]; }
    } else {
        const int* e = (const int*)eiv;
        s0 = e[e0];
        d0 = e[E + e0];
        if (has1) { s1 = e[e0 + 1]; d1 = e[E + e0 + 1]; }
    }
    s0 = min(max(s0, 0), N - 1); d0 = min(max(d0, 0), N - 1);
    g_src[e0] = s0; g_dst[e0] = d0;
    g_rank[e0] = atomicAdd(&g_deg[d0], 1);
    if (has1) {
        s1 = min(max(s1, 0), N - 1); d1 = min(max(d1, 0), N - 1);
        g_src[e0 + 1] = s1; g_dst[e0 + 1] = d1;
        g_rank[e0 + 1] = atomicAdd(&g_deg[d1], 1);
    }
}

// fat kernel: gemm1 blocks [0, ngemm) + ingest blocks [ngemm, ...)
__global__ __launch_bounds__(256)
void k_fat(const float* __restrict__ X, const float* __restrict__ W,
           const float* __restrict__ avs, const float* __restrict__ avd,
           const void* __restrict__ eiv, int N, int E, int ngemm) {
    if ((int)blockIdx.x < ngemm)
        gemm_body<128>(X, W, avs, avd, N, blockIdx.x);
    else
        ingest_body(eiv, E, N, blockIdx.x - ngemm);
}

__global__ __launch_bounds__(256)
void k_gemm2(const float* __restrict__ X, const float* __restrict__ W,
             const float* __restrict__ avs, const float* __restrict__ avd, int N) {
    gemm_body<64>(X, W, avs, avd, N, blockIdx.x);
}

// ---------------- scan (self-cleaning: zeroes g_deg after reading) -------------------
__global__ void k_scan() {
    __shared__ int warp_red[32];
    __shared__ int s_carry;
    int tid = threadIdx.x, lane = tid & 31, wid = tid >> 5;
    if (tid == 0) s_carry = 0;
    __syncthreads();
    int4* deg4 = (int4*)g_deg;
    int4* row4 = (int4*)g_row;
    const int total4 = NMAX / 4;
    for (int base = 0; base < total4; base += 1024) {
        int idx = base + tid;
        int4 v = (idx < total4) ? deg4[idx] : make_int4(0, 0, 0, 0);
        if (idx < total4) deg4[idx] = make_int4(0, 0, 0, 0);
        int s = v.x + v.y + v.z + v.w;
        int x = s;
#pragma unroll
        for (int o = 1; o < 32; o <<= 1) {
            int t = __shfl_up_sync(0xFFFFFFFFu, x, o);
            if (lane >= o) x += t;
        }
        if (lane == 31) warp_red[wid] = x;
        __syncthreads();
        if (wid == 0) {
            int w = warp_red[lane];
#pragma unroll
            for (int o = 1; o < 32; o <<= 1) {
                int t = __shfl_up_sync(0xFFFFFFFFu, w, o);
                if (lane >= o) w += t;
            }
            warp_red[lane] = w;
        }
        __syncthreads();
        int wsum = (wid > 0) ? warp_red[wid - 1] : 0;
        int incl = x + wsum;
        int carry = s_carry;
        if (idx < total4) {
            int e0 = carry + incl - s;
            int4 r;
            r.x = e0;
            r.y = e0 + v.x;
            r.z = e0 + v.x + v.y;
            r.w = e0 + v.x + v.y + v.z;
            row4[idx] = r;
        }
        __syncthreads();
        if (tid == 1023) s_carry = carry + incl;
        __syncthreads();
    }
}

// atomic-free scatter, 4 edges/thread (int4 loads; MLP=4)
__global__ void k_scatter(int E) {
    int i = blockIdx.x * 256 + threadIdx.x;
    int nvec = E >> 2;
    if (i < nvec) {
        int4 d = ((const int4*)g_dst)[i];
        int4 r = ((const int4*)g_rank)[i];
        int4 s = ((const int4*)g_src)[i];
        int b0 = g_row[d.x], b1 = g_row[d.y], b2 = g_row[d.z], b3 = g_row[d.w];
        g_ssrc[b0 + r.x] = s.x;
        g_ssrc[b1 + r.y] = s.y;
        g_ssrc[b2 + r.z] = s.z;
        g_ssrc[b3 + r.w] = s.w;
    } else if (i == nvec) {
        for (int e = nvec * 4; e < E; e++)
            g_ssrc[g_row[g_dst[e]] + g_rank[e]] = g_src[e];
    }
}

// ---------------- fused GAT aggregation: one warp per dst node, LDG.64 pair scheme --
// Half-warps serve alternating edges: lanes [0,16) -> edge u, lanes [16,32) -> u+1.
// Each lane loads uint2 = 4 fp16 channels of its edge's h-row (one warp LDG.64 covers
// 2 edges). One SHFL with lane-dependent index delivers per-half-warp p and offset.
// Scalar-FFMA accumulation (R11's packed-chain regression avoided).
__global__ void k_gat(const float* __restrict__ bias, float* __restrict__ outbuf,
                      int do_relu, int N) {
    int warp = (blockIdx.x * blockDim.x + threadIdx.x) >> 5;
    int lane = threadIdx.x & 31;
    if (warp >= N) return;
    int beg = g_row[warp], end = g_row[warp + 1];
    float ad = g_ad[warp];
    const uint2* h2v = (const uint2*)g_h2;   // 16 uint2 per node row
    int qx = lane & 15;
    int half = lane >> 4;

    float a0 = 0.f, a1 = 0.f, a2 = 0.f, a3 = 0.f;   // 4 channels: qx*4 .. +3
    float ssum = 0.f;
    for (int base = beg; base < end; base += 32) {
        int i = base + lane;
        float p = 0.f;
        int off = 0;
        if (i < end) {
            int s = g_ssrc[i];
            float e = g_as[s] + ad;
            e = (e > 0.f) ? e : 0.2f * e;      // LeakyReLU(0.2)
            p = __expf(e);
            ssum += p;
            off = s * 16;                       // row offset in uint2 units
        }
        int cnt = min(32, end - base);
        for (int u = 0; u < cnt; u += 8) {      // 8 edges per iter = 4 LDG.64 (MLP 4)
            uint2 hw[4]; float pw[4];
#pragma unroll
            for (int v = 0; v < 4; v++) {
                int j = u + v * 2 + half;                    // this half-warp's edge
                pw[v] = __shfl_sync(0xFFFFFFFFu, p, j);      // p=0 beyond cnt
                int ov = __shfl_sync(0xFFFFFFFFu, off, j);
                hw[v] = h2v[ov + qx];
            }
#pragma unroll
            for (int v = 0; v < 4; v++) {
                float2 fa = __half22float2(*reinterpret_cast<__half2*>(&hw[v].x));
                float2 fb = __half22float2(*reinterpret_cast<__half2*>(&hw[v].y));
                a0 += pw[v] * fa.x;
                a1 += pw[v] * fa.y;
                a2 += pw[v] * fb.x;
                a3 += pw[v] * fb.y;
            }
        }
    }
#pragma unroll
    for (int o = 16; o > 0; o >>= 1)
        ssum += __shfl_xor_sync(0xFFFFFFFFu, ssum, o);

    // merge the two half-warps' partial channel sums
    a0 += __shfl_xor_sync(0xFFFFFFFFu, a0, 16);
    a1 += __shfl_xor_sync(0xFFFFFFFFu, a1, 16);
    a2 += __shfl_xor_sync(0xFFFFFFFFu, a2, 16);
    a3 += __shfl_xor_sync(0xFFFFFFFFu, a3, 16);

    if (half == 0) {
        float inv = 1.f / (ssum + 1e-16f);   // deg==0: acc=0 -> out=bias, matches ref
        float4 bv = ((const float4*)bias)[qx];
        float4 r;
        r.x = a0 * inv + bv.x;
        r.y = a1 * inv + bv.y;
        r.z = a2 * inv + bv.z;
        r.w = a3 * inv + bv.w;
        if (do_relu) {
            r.x = fmaxf(r.x, 0.f); r.y = fmaxf(r.y, 0.f);
            r.z = fmaxf(r.z, 0.f); r.w = fmaxf(r.w, 0.f);
        }
        ((float4*)outbuf)[warp * 16 + qx] = r;
    }
}

// ---------------- launch -------------------------------------------------------------
extern "C" void kernel_launch(void* const* d_in, const int* in_sizes, int n_in,
                              void* d_out, int out_size) {
    // ---- size-driven role assignment (robust to metadata ordering) ----
    int ix = 0, ie = 0, iw1 = 0, iw2 = 0;
    for (int i = 1; i < n_in; i++) if (in_sizes[i] > in_sizes[ix]) ix = i;
    ie = (ix == 0) ? 1 : 0;
    for (int i = 0; i < n_in; i++) if (i != ix && in_sizes[i] > in_sizes[ie]) ie = i;
    iw1 = -1;
    for (int i = 0; i < n_in; i++) {
        if (i == ix || i == ie) continue;
        if (iw1 < 0 || in_sizes[i] > in_sizes[iw1]) iw1 = i;
    }
    iw2 = -1;
    for (int i = 0; i < n_in; i++) {
        if (i == ix || i == ie || i == iw1) continue;
        if (iw2 < 0 || in_sizes[i] > in_sizes[iw2]) iw2 = i;
    }
    int rv[6]; int nrv = 0;
    for (int i = 0; i < n_in && nrv < 6; i++)
        if (i != ix && i != ie && i != iw1 && i != iw2) rv[nrv++] = i;

    int ias1, iad1, ib1, ias2, iad2, ib2;
    if (ix == 0) {  // signature/dict order
        ias1 = rv[0]; iad1 = rv[1]; ib1 = rv[2];
        ias2 = rv[3]; iad2 = rv[4]; ib2 = rv[5];
    } else {        // alphabetical order
        iad1 = rv[0]; iad2 = rv[1]; ias1 = rv[2];
        ias2 = rv[3]; ib1  = rv[4]; ib2  = rv[5];
    }

    const float* x   = (const float*)d_in[ix];
    const void*  ei  = d_in[ie];
    const float* W1  = (const float*)d_in[iw1];
    const float* as1 = (const float*)d_in[ias1];
    const float* ad1 = (const float*)d_in[iad1];
    const float* b1  = (const float*)d_in[ib1];
    const float* W2  = (const float*)d_in[iw2];
    const float* as2 = (const float*)d_in[ias2];
    const float* ad2 = (const float*)d_in[iad2];
    const float* b2  = (const float*)d_in[ib2];
    float*       out = (float*)d_out;

    const int Hd  = in_sizes[ias1];         // 64
    const int Fin = in_sizes[iw1] / Hd;     // 128
    const int N   = in_sizes[ix] / Fin;     // 50000
    const int E   = in_sizes[ie] / 2;       // 800000

    float* p_x2 = nullptr;
    cudaGetSymbolAddress((void**)&p_x2, g_x2);

    const int NGEMM   = (N + 127) / 128;
    const int NING    = (E + 511) / 512;
    const int B_E4    = (E / 4 + 1 + 255) / 256;
    const int B_WARP  = (N * 32 + 255) / 256;

    // 6 launches; slot 4 (= ncu capture window) lands on the NEW k_gat (layer 1).
    k_fat<<<NGEMM + NING, 256>>>(x, W1, as1, ad1, ei, N, E, NGEMM);  // 1
    k_scan<<<1, 1024>>>();                                            // 2
    k_scatter<<<B_E4, 256>>>(E);                                      // 3
    k_gat<<<B_WARP, 256>>>(b1, p_x2, 1, N);                           // 4 <- profiled
    k_gemm2<<<NGEMM, 256>>>(p_x2, W2, as2, ad2, N);                   // 5
    k_gat<<<B_WARP, 256>>>(b2, out, 0, N);                            // 6
}